// round 3
// baseline (speedup 1.0000x reference)
#include <cuda_runtime.h>

#define NN 50000
#define EE 640000
#define HCC 128
#define NHH 4
#define NLAY 4
#define NBATCH 64
#define NCLS 88

// ---------------- scratch (static device globals; no allocation) ----------------
__device__ float g_h[NN * HCC];        // current node features
__device__ float g_hp[NN * HCC];       // per-layer projection h @ Wl
__device__ float g_asrc[NN * NHH];
__device__ float g_adst[NN * NHH];
__device__ float g_aedge[EE * NHH];    // stored in CSR order
__device__ int   g_deg[NN];
__device__ int   g_off[NN + 1];
__device__ int   g_cur[NN];
__device__ int   g_csr_src[EE];
__device__ int   g_csr_eid[EE];
__device__ float g_M[HCC * NHH];
__device__ float g_sums[NBATCH * HCC];
__device__ float g_cnt[NBATCH];

// ---------------- small helpers ----------------
__device__ __forceinline__ void softmax_upd(float& m, float& d, float a) {
    float nm = fmaxf(m, a);
    d = ((m == nm) ? d : d * __expf(m - nm)) + __expf(a - nm);
    m = nm;
}
__device__ __forceinline__ void softmax_comb(float& m, float& d, float om, float od) {
    float nm = fmaxf(m, om);
    float t1 = (m == nm) ? d : d * __expf(m - nm);
    float t2 = (om == nm) ? od : od * __expf(om - nm);
    m = nm; d = t1 + t2;
}

// ---------------- CSR build ----------------
__global__ void k_zero_deg() {
    int i = blockIdx.x * blockDim.x + threadIdx.x;
    if (i < NN) g_deg[i] = 0;
}
__global__ void k_hist(const int* __restrict__ dst) {
    int i = blockIdx.x * blockDim.x + threadIdx.x;
    if (i < EE) atomicAdd(&g_deg[dst[i]], 1);
}
__global__ void k_scan() {
    __shared__ int sm[1024];
    __shared__ int s_run;
    int t = threadIdx.x;
    if (t == 0) s_run = 0;
    __syncthreads();
    for (int base = 0; base < NN; base += 1024) {
        int v = (base + t < NN) ? g_deg[base + t] : 0;
        sm[t] = v;
        __syncthreads();
        for (int o = 1; o < 1024; o <<= 1) {
            int x = (t >= o) ? sm[t - o] : 0;
            __syncthreads();
            sm[t] += x;
            __syncthreads();
        }
        int tot = sm[1023];
        int base_run = s_run;
        int excl = sm[t] - v + base_run;
        if (base + t < NN) { g_off[base + t] = excl; g_cur[base + t] = excl; }
        __syncthreads();
        if (t == 0) s_run = base_run + tot;
        __syncthreads();
    }
    if (t == 0) g_off[NN] = s_run;
}
__global__ void k_scatter(const int* __restrict__ src, const int* __restrict__ dst) {
    int i = blockIdx.x * blockDim.x + threadIdx.x;
    if (i < EE) {
        int p = atomicAdd(&g_cur[dst[i]], 1);
        g_csr_src[p] = src[i];
        g_csr_eid[p] = i;
    }
}

// ---------------- node encoder: relu(LN(x @ W_ne + b_ne)) ----------------
__global__ void k_node_enc(const float* __restrict__ x, const float* __restrict__ W,
                           const float* __restrict__ b, const float* __restrict__ g,
                           const float* __restrict__ be) {
    int t = threadIdx.x;
    int n = blockIdx.x * 8 + (t >> 5);
    if (n >= NN) return;
    int lane = t & 31;
    float4 xv = ((const float4*)x)[n];
    const float4* Wr = (const float4*)W;
    float4 w0 = Wr[lane], w1 = Wr[32 + lane], w2 = Wr[64 + lane], w3 = Wr[96 + lane];
    float4 bv = ((const float4*)b)[lane];
    float4 y;
    y.x = bv.x + xv.x * w0.x + xv.y * w1.x + xv.z * w2.x + xv.w * w3.x;
    y.y = bv.y + xv.x * w0.y + xv.y * w1.y + xv.z * w2.y + xv.w * w3.y;
    y.z = bv.z + xv.x * w0.z + xv.y * w1.z + xv.z * w2.z + xv.w * w3.z;
    y.w = bv.w + xv.x * w0.w + xv.y * w1.w + xv.z * w2.w + xv.w * w3.w;
    float s1 = y.x + y.y + y.z + y.w;
    float s2 = y.x * y.x + y.y * y.y + y.z * y.z + y.w * y.w;
    #pragma unroll
    for (int o = 16; o; o >>= 1) {
        s1 += __shfl_xor_sync(~0u, s1, o);
        s2 += __shfl_xor_sync(~0u, s2, o);
    }
    float mean = s1 * (1.f / HCC);
    float var = s2 * (1.f / HCC) - mean * mean;
    float rstd = rsqrtf(var + 1e-5f);
    float4 gv = ((const float4*)g)[lane];
    float4 bev = ((const float4*)be)[lane];
    float4 r;
    r.x = fmaxf((y.x - mean) * rstd * gv.x + bev.x, 0.f);
    r.y = fmaxf((y.y - mean) * rstd * gv.y + bev.y, 0.f);
    r.z = fmaxf((y.z - mean) * rstd * gv.z + bev.z, 0.f);
    r.w = fmaxf((y.w - mean) * rstd * gv.w + bev.w, 0.f);
    ((float4*)g_h)[n * 32 + lane] = r;
}

// ---------------- per-layer: M[k,h] = sum_c We[k, h*32+c] * att_e[h,c] ----------------
__global__ void k_Ml(const float* __restrict__ We_l, const float* __restrict__ atte_l) {
    int k = threadIdx.x;
    #pragma unroll
    for (int h = 0; h < NHH; h++) {
        float m = 0.f;
        #pragma unroll
        for (int c = 0; c < 32; c++)
            m += We_l[k * HCC + h * 32 + c] * atte_l[h * 32 + c];
        g_M[k * NHH + h] = m;
    }
}

// ---------------- per-layer: a_edge in CSR order ----------------
__global__ void k_aedge(const float* __restrict__ eattr, const float* __restrict__ Wee,
                        const float* __restrict__ bee) {
    __shared__ float sW[HCC], sB[HCC];
    __shared__ float4 sM[HCC];
    int t = threadIdx.x;
    if (t < HCC) { sW[t] = Wee[t]; sB[t] = bee[t]; }
    for (int i = t; i < HCC; i += blockDim.x) sM[i] = ((const float4*)g_M)[i];
    __syncthreads();
    int p = blockIdx.x * blockDim.x + t;
    if (p >= EE) return;
    int eid = g_csr_eid[p];
    float tv = eattr[eid];
    float a0 = 0, a1 = 0, a2 = 0, a3 = 0;
    #pragma unroll 4
    for (int k = 0; k < HCC; k++) {
        float ef = fmaxf(fmaf(tv, sW[k], sB[k]), 0.f);
        float4 m = sM[k];
        a0 += ef * m.x; a1 += ef * m.y; a2 += ef * m.z; a3 += ef * m.w;
    }
    ((float4*)g_aedge)[p] = make_float4(a0, a1, a2, a3);
}

// ---------------- per-layer GEMM: g_hp = g_h @ W (N x 128 x 128) ----------------
#define GBM 64
__global__ __launch_bounds__(256) void k_gemm(const float* __restrict__ W) {
    extern __shared__ float smem[];
    float* Ws = smem;                  // 128*128
    float* Xs = smem + HCC * HCC;      // 64*128
    int t = threadIdx.x;
    int base = blockIdx.x * GBM;
    float4* Ws4 = (float4*)Ws;
    const float4* W4 = (const float4*)W;
    #pragma unroll
    for (int i = 0; i < 16; i++) Ws4[t + 256 * i] = W4[t + 256 * i];
    float4* Xs4 = (float4*)Xs;
    #pragma unroll
    for (int i = 0; i < 8; i++) {
        int idx = t + 256 * i;           // float4 index, 32 per row
        int r = base + (idx >> 5);
        float4 v = make_float4(0, 0, 0, 0);
        if (r < NN) v = ((const float4*)g_h)[r * 32 + (idx & 31)];
        Xs4[idx] = v;
    }
    __syncthreads();
    int tx = t & 15, ty = t >> 4;        // cols tx*8..+7, rows ty*4..+3
    float acc[4][8];
    #pragma unroll
    for (int i = 0; i < 4; i++)
        #pragma unroll
        for (int j = 0; j < 8; j++) acc[i][j] = 0.f;
    #pragma unroll 4
    for (int k = 0; k < HCC; k++) {
        float4 b0 = *(float4*)&Ws[k * HCC + tx * 8];
        float4 b1 = *(float4*)&Ws[k * HCC + tx * 8 + 4];
        float a[4];
        #pragma unroll
        for (int i = 0; i < 4; i++) a[i] = Xs[(ty * 4 + i) * HCC + k];
        #pragma unroll
        for (int i = 0; i < 4; i++) {
            acc[i][0] += a[i] * b0.x; acc[i][1] += a[i] * b0.y;
            acc[i][2] += a[i] * b0.z; acc[i][3] += a[i] * b0.w;
            acc[i][4] += a[i] * b1.x; acc[i][5] += a[i] * b1.y;
            acc[i][6] += a[i] * b1.z; acc[i][7] += a[i] * b1.w;
        }
    }
    #pragma unroll
    for (int i = 0; i < 4; i++) {
        int r = base + ty * 4 + i;
        if (r < NN) {
            *(float4*)&g_hp[r * HCC + tx * 8]     = make_float4(acc[i][0], acc[i][1], acc[i][2], acc[i][3]);
            *(float4*)&g_hp[r * HCC + tx * 8 + 4] = make_float4(acc[i][4], acc[i][5], acc[i][6], acc[i][7]);
        }
    }
}

// ---------------- per-layer: a_src / a_dst from g_hp ----------------
__global__ void k_attn(const float* __restrict__ atts, const float* __restrict__ attd) {
    __shared__ float ss[HCC], sd[HCC];
    int t = threadIdx.x;
    if (t < HCC) { ss[t] = atts[t]; sd[t] = attd[t]; }
    __syncthreads();
    int n = blockIdx.x * 8 + (t >> 5);
    if (n >= NN) return;
    int lane = t & 31;
    float4 p = ((const float4*)g_hp)[n * 32 + lane];
    int c = lane * 4;
    float vs = p.x * ss[c] + p.y * ss[c + 1] + p.z * ss[c + 2] + p.w * ss[c + 3];
    float vd = p.x * sd[c] + p.y * sd[c + 1] + p.z * sd[c + 2] + p.w * sd[c + 3];
    #pragma unroll
    for (int o = 4; o; o >>= 1) {
        vs += __shfl_xor_sync(~0u, vs, o);
        vd += __shfl_xor_sync(~0u, vd, o);
    }
    if ((lane & 7) == 0) {
        g_asrc[n * NHH + (lane >> 3)] = vs;
        g_adst[n * NHH + (lane >> 3)] = vd;
    }
}

// ---------------- per-layer: softmax-aggregate + bias + LN + relu + residual ----------------
__global__ void k_agg(const float* __restrict__ bias, const float* __restrict__ gam,
                      const float* __restrict__ bet) {
    int t = threadIdx.x;
    int n = blockIdx.x * 8 + (t >> 5);
    if (n >= NN) return;
    int lane = t & 31;
    int o0 = g_off[n];
    int deg = g_off[n + 1] - o0;
    float4 adn = *(float4*)&g_adst[n * NHH];

    const float NEG = -1e30f;
    float m0 = NEG, m1 = NEG, m2 = NEG, m3 = NEG;
    float d0 = 0, d1 = 0, d2 = 0, d3 = 0;
    for (int j = lane; j < deg; j += 32) {
        int s = g_csr_src[o0 + j];
        float4 as = *(float4*)&g_asrc[s * NHH];
        float4 ae = ((const float4*)g_aedge)[o0 + j];
        float a0 = as.x + adn.x + ae.x; a0 = a0 >= 0.f ? a0 : 0.2f * a0;
        float a1 = as.y + adn.y + ae.y; a1 = a1 >= 0.f ? a1 : 0.2f * a1;
        float a2 = as.z + adn.z + ae.z; a2 = a2 >= 0.f ? a2 : 0.2f * a2;
        float a3 = as.w + adn.w + ae.w; a3 = a3 >= 0.f ? a3 : 0.2f * a3;
        softmax_upd(m0, d0, a0); softmax_upd(m1, d1, a1);
        softmax_upd(m2, d2, a2); softmax_upd(m3, d3, a3);
    }
    #pragma unroll
    for (int o = 16; o; o >>= 1) {
        float om, od;
        om = __shfl_xor_sync(~0u, m0, o); od = __shfl_xor_sync(~0u, d0, o); softmax_comb(m0, d0, om, od);
        om = __shfl_xor_sync(~0u, m1, o); od = __shfl_xor_sync(~0u, d1, o); softmax_comb(m1, d1, om, od);
        om = __shfl_xor_sync(~0u, m2, o); od = __shfl_xor_sync(~0u, d2, o); softmax_comb(m2, d2, om, od);
        om = __shfl_xor_sync(~0u, m3, o); od = __shfl_xor_sync(~0u, d3, o); softmax_comb(m3, d3, om, od);
    }
    float rd0 = d0 > 0.f ? 1.f / d0 : 0.f;
    float rd1 = d1 > 0.f ? 1.f / d1 : 0.f;
    float rd2 = d2 > 0.f ? 1.f / d2 : 0.f;
    float rd3 = d3 > 0.f ? 1.f / d3 : 0.f;

    int hh = lane >> 3;
    float mh  = (hh & 2) ? ((hh & 1) ? m3 : m2) : ((hh & 1) ? m1 : m0);
    float rdh = (hh & 2) ? ((hh & 1) ? rd3 : rd2) : ((hh & 1) ? rd1 : rd0);
    float adh = (hh & 2) ? ((hh & 1) ? adn.w : adn.z) : ((hh & 1) ? adn.y : adn.x);

    float4 acc = make_float4(0, 0, 0, 0);
    #pragma unroll 2
    for (int j = 0; j < deg; j++) {
        int p = o0 + j;
        int s = g_csr_src[p];
        float a = g_asrc[s * NHH + hh] + adh + g_aedge[p * NHH + hh];
        a = a >= 0.f ? a : 0.2f * a;
        float w = __expf(a - mh) * rdh;
        float4 hp = ((const float4*)g_hp)[s * 32 + lane];
        acc.x += w * hp.x; acc.y += w * hp.y; acc.z += w * hp.z; acc.w += w * hp.w;
    }

    // bias + LayerNorm + relu + residual
    float4 bv = ((const float4*)bias)[lane];
    float4 v = make_float4(acc.x + bv.x, acc.y + bv.y, acc.z + bv.z, acc.w + bv.w);
    float s1 = v.x + v.y + v.z + v.w;
    float s2 = v.x * v.x + v.y * v.y + v.z * v.z + v.w * v.w;
    #pragma unroll
    for (int o = 16; o; o >>= 1) {
        s1 += __shfl_xor_sync(~0u, s1, o);
        s2 += __shfl_xor_sync(~0u, s2, o);
    }
    float mean = s1 * (1.f / HCC);
    float var = s2 * (1.f / HCC) - mean * mean;
    float rstd = rsqrtf(var + 1e-5f);
    float4 gv = ((const float4*)gam)[lane];
    float4 bev = ((const float4*)bet)[lane];
    float4 hold = ((const float4*)g_h)[n * 32 + lane];
    float4 r;
    r.x = hold.x + fmaxf((v.x - mean) * rstd * gv.x + bev.x, 0.f);
    r.y = hold.y + fmaxf((v.y - mean) * rstd * gv.y + bev.y, 0.f);
    r.z = hold.z + fmaxf((v.z - mean) * rstd * gv.z + bev.z, 0.f);
    r.w = hold.w + fmaxf((v.w - mean) * rstd * gv.w + bev.w, 0.f);
    ((float4*)g_h)[n * 32 + lane] = r;
}

// ---------------- pooling + classifier ----------------
__global__ void k_zero_pool() {
    int i = blockIdx.x * blockDim.x + threadIdx.x;
    if (i < NBATCH * HCC) g_sums[i] = 0.f;
    if (i < NBATCH) g_cnt[i] = 0.f;
}
__global__ void k_count(const int* __restrict__ batch) {
    int i = blockIdx.x * blockDim.x + threadIdx.x;
    if (i < NN) atomicAdd(&g_cnt[batch[i]], 1.f);
}
__global__ void k_pool(const int* __restrict__ batch) {
    int n0 = blockIdx.x * 512;
    int n1 = n0 + 512; if (n1 > NN) n1 = NN;
    int c = threadIdx.x;
    float run = 0.f;
    int curb = batch[n0];
    for (int n = n0; n < n1; n++) {
        int b = batch[n];
        if (b != curb) {
            atomicAdd(&g_sums[curb * HCC + c], run);
            run = 0.f; curb = b;
        }
        run += g_h[n * HCC + c];
    }
    atomicAdd(&g_sums[curb * HCC + c], run);
}
__global__ void k_cls(const float* __restrict__ W1, const float* __restrict__ b1,
                      const float* __restrict__ W2, const float* __restrict__ b2,
                      float* __restrict__ out) {
    __shared__ float sp[HCC];
    __shared__ float sz[64];
    int b = blockIdx.x;
    int c = threadIdx.x;
    float cnt = fmaxf(g_cnt[b], 1.f);
    sp[c] = g_sums[b * HCC + c] / cnt;
    __syncthreads();
    if (c < 64) {
        float a = b1[c];
        #pragma unroll 4
        for (int k = 0; k < HCC; k++) a += sp[k] * W1[k * 64 + c];
        sz[c] = fmaxf(a, 0.f);
    }
    __syncthreads();
    if (c < NCLS) {
        float a = b2[c];
        #pragma unroll 4
        for (int k = 0; k < 64; k++) a += sz[k] * W2[k * NCLS + c];
        out[b * NCLS + c] = a;
    }
}

// ---------------- launch ----------------
extern "C" void kernel_launch(void* const* d_in, const int* in_sizes, int n_in,
                              void* d_out, int out_size) {
    (void)in_sizes; (void)n_in; (void)out_size;
    const float* x     = (const float*)d_in[0];
    const float* eattr = (const float*)d_in[1];
    const int*   eidx  = (const int*)d_in[2];
    const int*   batch = (const int*)d_in[3];
    const float* W_ne  = (const float*)d_in[4];
    const float* b_ne  = (const float*)d_in[5];
    const float* g_ne  = (const float*)d_in[6];
    const float* be_ne = (const float*)d_in[7];
    const float* W_ee  = (const float*)d_in[8];
    const float* b_ee  = (const float*)d_in[9];
    const float* Wl    = (const float*)d_in[10];
    const float* att_s = (const float*)d_in[11];
    const float* att_d = (const float*)d_in[12];
    const float* We    = (const float*)d_in[13];
    const float* att_e = (const float*)d_in[14];
    const float* b_l   = (const float*)d_in[15];
    const float* g_l   = (const float*)d_in[16];
    const float* be_l  = (const float*)d_in[17];
    const float* W1    = (const float*)d_in[18];
    const float* b1    = (const float*)d_in[19];
    const float* W2    = (const float*)d_in[20];
    const float* b2    = (const float*)d_in[21];
    float* out = (float*)d_out;

    const int* src = eidx;
    const int* dst = eidx + EE;

    const int SMEM_GEMM = (HCC * HCC + GBM * HCC) * 4;   // 98304 bytes
    cudaFuncSetAttribute(k_gemm, cudaFuncAttributeMaxDynamicSharedMemorySize, SMEM_GEMM);

    // CSR build (once per launch; edge_index is constant across layers)
    k_zero_deg<<<(NN + 255) / 256, 256>>>();
    k_hist<<<(EE + 255) / 256, 256>>>(dst);
    k_scan<<<1, 1024>>>();
    k_scatter<<<(EE + 255) / 256, 256>>>(src, dst);

    // encoders
    k_node_enc<<<(NN + 7) / 8, 256>>>(x, W_ne, b_ne, g_ne, be_ne);

    for (int l = 0; l < NLAY; l++) {
        k_Ml<<<1, HCC>>>(We + l * HCC * HCC, att_e + l * HCC);
        k_aedge<<<(EE + 255) / 256, 256>>>(eattr, W_ee, b_ee);
        k_gemm<<<(NN + GBM - 1) / GBM, 256, SMEM_GEMM>>>(Wl + l * HCC * HCC);
        k_attn<<<(NN + 7) / 8, 256>>>(att_s + l * HCC, att_d + l * HCC);
        k_agg<<<(NN + 7) / 8, 256>>>(b_l + l * HCC, g_l + l * HCC, be_l + l * HCC);
    }

    // pooling + classifier
    k_zero_pool<<<(NBATCH * HCC + 255) / 256, 256>>>();
    k_count<<<(NN + 255) / 256, 256>>>(batch);
    k_pool<<<(NN + 511) / 512, HCC>>>(batch);
    k_cls<<<NBATCH, HCC>>>(W1, b1, W2, b2, out);
}

// round 4
// speedup vs baseline: 1.3402x; 1.3402x over previous
#include <cuda_runtime.h>

#define NN 50000
#define EE 640000
#define HCC 128
#define NHH 4
#define NLAY 4
#define NBATCH 64
#define NCLS 88

// ---------------- scratch (static device globals; no allocation) ----------------
__device__ float g_h[NN * HCC];
__device__ float g_hp[NN * HCC];
__device__ float g_asrc[NN * NHH];
__device__ float g_adst[NN * NHH];
__device__ float4 g_aedge_all[NLAY * EE];    // per-layer, CSR order
__device__ int   g_deg[NN];
__device__ int   g_off[NN + 1];
__device__ int   g_cur[NN];
__device__ int   g_bsum[64];
__device__ int   g_csr_src[EE];
__device__ float g_tcsr[EE];                 // edge_attr value in CSR order
__device__ float g_sums[NBATCH * HCC];
__device__ float g_cnt[NBATCH];

// piecewise-linear a_edge tables
__device__ int   d_np, d_nn2;
__device__ float d_thrp[HCC], d_thrn[HCC];
__device__ float4 d_PA[(HCC + 1) * NLAY];
__device__ float4 d_PB[(HCC + 1) * NLAY];
__device__ float4 d_SA[(HCC + 1) * NLAY];
__device__ float4 d_SB[(HCC + 1) * NLAY];
__device__ float4 d_CB[NLAY];

// ---------------- helpers ----------------
__device__ __forceinline__ void softmax_upd(float& m, float& d, float a) {
    float nm = fmaxf(m, a);
    d = ((m == nm) ? d : d * __expf(m - nm)) + __expf(a - nm);
    m = nm;
}
__device__ __forceinline__ void softmax_comb(float& m, float& d, float om, float od) {
    float nm = fmaxf(m, om);
    float t1 = (m == nm) ? d : d * __expf(m - nm);
    float t2 = (om == nm) ? od : od * __expf(om - nm);
    m = nm; d = t1 + t2;
}

// ---------------- zero ----------------
__global__ void k_zero() {
    int i = blockIdx.x * blockDim.x + threadIdx.x;
    if (i < NN) g_deg[i] = 0;
    if (i < NBATCH * HCC) g_sums[i] = 0.f;
    if (i < NBATCH) g_cnt[i] = 0.f;
}

// ---------------- CSR build ----------------
__global__ void k_hist(const int* __restrict__ dst) {
    int i = blockIdx.x * blockDim.x + threadIdx.x;
    if (i < EE) atomicAdd(&g_deg[dst[i]], 1);
}
// block-level scan: 49 blocks x 1024
__global__ void k_scan1() {
    __shared__ int ws[32];
    int t = threadIdx.x;
    int gi = blockIdx.x * 1024 + t;
    int v = (gi < NN) ? g_deg[gi] : 0;
    int lane = t & 31, wid = t >> 5;
    int x = v;
    #pragma unroll
    for (int o = 1; o < 32; o <<= 1) {
        int y = __shfl_up_sync(~0u, x, o);
        if (lane >= o) x += y;
    }
    if (lane == 31) ws[wid] = x;
    __syncthreads();
    if (wid == 0) {
        int y = ws[lane];
        #pragma unroll
        for (int o = 1; o < 32; o <<= 1) {
            int z = __shfl_up_sync(~0u, y, o);
            if (lane >= o) y += z;
        }
        ws[lane] = y;
    }
    __syncthreads();
    int excl = x - v + (wid ? ws[wid - 1] : 0);
    if (gi < NN) g_off[gi] = excl;
    if (t == 1023) g_bsum[blockIdx.x] = excl + v;
}
__global__ void k_scan2() {
    __shared__ int sm2[64];
    int t = threadIdx.x;
    int v = (t < 49) ? g_bsum[t] : 0;
    sm2[t] = v;
    __syncthreads();
    #pragma unroll
    for (int o = 1; o < 64; o <<= 1) {
        int x = (t >= o) ? sm2[t - o] : 0;
        __syncthreads();
        sm2[t] += x;
        __syncthreads();
    }
    if (t < 49) g_bsum[t] = sm2[t] - v;
}
__global__ void k_scan3() {
    int i = blockIdx.x * blockDim.x + threadIdx.x;
    if (i < NN) {
        int o = g_off[i] + g_bsum[i >> 10];
        g_off[i] = o;
        g_cur[i] = o;
    }
    if (i == 0) g_off[NN] = EE;
}
__global__ void k_scatter(const int* __restrict__ src, const int* __restrict__ dst,
                          const float* __restrict__ eattr) {
    int i = blockIdx.x * blockDim.x + threadIdx.x;
    if (i < EE) {
        int p = atomicAdd(&g_cur[dst[i]], 1);
        g_csr_src[p] = src[i];
        g_tcsr[p] = eattr[i];
    }
}

// ---------------- node encoder ----------------
__global__ void k_node_enc(const float* __restrict__ x, const float* __restrict__ W,
                           const float* __restrict__ b, const float* __restrict__ g,
                           const float* __restrict__ be) {
    int t = threadIdx.x;
    int n = blockIdx.x * 8 + (t >> 5);
    if (n >= NN) return;
    int lane = t & 31;
    float4 xv = ((const float4*)x)[n];
    const float4* Wr = (const float4*)W;
    float4 w0 = Wr[lane], w1 = Wr[32 + lane], w2 = Wr[64 + lane], w3 = Wr[96 + lane];
    float4 bv = ((const float4*)b)[lane];
    float4 y;
    y.x = bv.x + xv.x * w0.x + xv.y * w1.x + xv.z * w2.x + xv.w * w3.x;
    y.y = bv.y + xv.x * w0.y + xv.y * w1.y + xv.z * w2.y + xv.w * w3.y;
    y.z = bv.z + xv.x * w0.z + xv.y * w1.z + xv.z * w2.z + xv.w * w3.z;
    y.w = bv.w + xv.x * w0.w + xv.y * w1.w + xv.z * w2.w + xv.w * w3.w;
    float s1 = y.x + y.y + y.z + y.w;
    float s2 = y.x * y.x + y.y * y.y + y.z * y.z + y.w * y.w;
    #pragma unroll
    for (int o = 16; o; o >>= 1) {
        s1 += __shfl_xor_sync(~0u, s1, o);
        s2 += __shfl_xor_sync(~0u, s2, o);
    }
    float mean = s1 * (1.f / HCC);
    float var = s2 * (1.f / HCC) - mean * mean;
    float rstd = rsqrtf(var + 1e-5f);
    float4 gv = ((const float4*)g)[lane];
    float4 bev = ((const float4*)be)[lane];
    float4 r;
    r.x = fmaxf((y.x - mean) * rstd * gv.x + bev.x, 0.f);
    r.y = fmaxf((y.y - mean) * rstd * gv.y + bev.y, 0.f);
    r.z = fmaxf((y.z - mean) * rstd * gv.z + bev.z, 0.f);
    r.w = fmaxf((y.w - mean) * rstd * gv.w + bev.w, 0.f);
    ((float4*)g_h)[n * 32 + lane] = r;
}

// ---------------- piecewise a_edge: prep (1 block, 128 threads) ----------------
__global__ void k_prep(const float* __restrict__ We, const float* __restrict__ atte,
                       const float* __restrict__ Wee, const float* __restrict__ bee) {
    __shared__ float stau[HCC], sw_[HCC], sb_[HCC];
    __shared__ int sflag[HCC];
    __shared__ float swm[NLAY * NHH][HCC];
    __shared__ float sbm[NLAY * NHH][HCC];
    __shared__ int srtp[HCC], srtn[HCC];
    __shared__ int s_np, s_nn;
    int k = threadIdx.x;
    if (k == 0) { s_np = 0; s_nn = 0; }
    float w = Wee[k], b = bee[k];
    #pragma unroll
    for (int l = 0; l < NLAY; l++) {
        #pragma unroll
        for (int h = 0; h < NHH; h++) {
            float m = 0.f;
            #pragma unroll 8
            for (int c = 0; c < 32; c++)
                m += We[l * HCC * HCC + k * HCC + h * 32 + c] * atte[l * HCC + h * 32 + c];
            swm[l * NHH + h][k] = w * m;
            sbm[l * NHH + h][k] = b * m;
        }
    }
    sw_[k] = w; sb_[k] = b;
    int flag = (w > 0.f) ? 0 : ((w < 0.f) ? 1 : 2);
    sflag[k] = flag;
    stau[k] = (flag < 2) ? (-b / w) : 0.f;
    __syncthreads();
    // rank within class (stable)
    float tk = stau[k];
    int rank = 0, cnt = 0;
    if (flag < 2) {
        for (int j = 0; j < HCC; j++)
            if (sflag[j] == flag) {
                cnt++;
                if (stau[j] < tk || (stau[j] == tk && j < k)) rank++;
            }
    }
    if (flag == 0 && rank == 0) s_np = cnt;
    if (flag == 1 && rank == 0) s_nn = cnt;
    if (flag == 0) { srtp[rank] = k; d_thrp[rank] = tk; }
    if (flag == 1) { srtn[rank] = k; d_thrn[rank] = tk; }
    __syncthreads();
    int np = s_np, nn = s_nn;
    float* PAf = (float*)d_PA; float* PBf = (float*)d_PB;
    float* SAf = (float*)d_SA; float* SBf = (float*)d_SB;
    float* CBf = (float*)d_CB;
    if (k < 16) {                 // prefix sums for positive-slope set
        int c = k, l = k >> 2, h = k & 3;
        float ra = 0.f, rb = 0.f;
        PAf[(0 * NLAY + l) * 4 + h] = 0.f;
        PBf[(0 * NLAY + l) * 4 + h] = 0.f;
        for (int i = 0; i < np; i++) {
            int kk = srtp[i];
            ra += swm[c][kk]; rb += sbm[c][kk];
            PAf[((i + 1) * NLAY + l) * 4 + h] = ra;
            PBf[((i + 1) * NLAY + l) * 4 + h] = rb;
        }
    } else if (k < 32) {          // suffix sums for negative-slope set
        int c = k - 16, l = c >> 2, h = c & 3;
        float ra = 0.f, rb = 0.f;
        SAf[(nn * NLAY + l) * 4 + h] = 0.f;
        SBf[(nn * NLAY + l) * 4 + h] = 0.f;
        for (int i = nn - 1; i >= 0; i--) {
            int kk = srtn[i];
            ra += swm[c][kk]; rb += sbm[c][kk];
            SAf[(i * NLAY + l) * 4 + h] = ra;
            SBf[(i * NLAY + l) * 4 + h] = rb;
        }
    } else if (k < 48) {          // constants (w == 0, b > 0)
        int c = k - 32;
        float r = 0.f;
        for (int j = 0; j < HCC; j++)
            if (sflag[j] == 2 && sb_[j] > 0.f) r += sbm[c][j];
        CBf[c] = r;
    }
    if (k == 0) { d_np = np; d_nn2 = nn; }
}

// ---------------- a_edge for all 4 layers, one pass over edges ----------------
__global__ __launch_bounds__(256) void k_aedge_all() {
    __shared__ float sThp[HCC], sThn[HCC];
    __shared__ float4 sPA[(HCC + 1) * NLAY], sPB[(HCC + 1) * NLAY];
    __shared__ float4 sSA[(HCC + 1) * NLAY], sSB[(HCC + 1) * NLAY];
    __shared__ float4 sCB[NLAY];
    int t = threadIdx.x;
    for (int i = t; i < HCC; i += 256) { sThp[i] = d_thrp[i]; sThn[i] = d_thrn[i]; }
    for (int i = t; i < (HCC + 1) * NLAY; i += 256) {
        sPA[i] = d_PA[i]; sPB[i] = d_PB[i];
        sSA[i] = d_SA[i]; sSB[i] = d_SB[i];
    }
    if (t < NLAY) sCB[t] = d_CB[t];
    __syncthreads();
    int np = d_np, nn = d_nn2;
    for (int p = blockIdx.x * 256 + t; p < EE; p += gridDim.x * 256) {
        float tv = g_tcsr[p];
        int lo = 0, hi = np;
        while (lo < hi) { int mid = (lo + hi) >> 1; if (sThp[mid] < tv) lo = mid + 1; else hi = mid; }
        int i = lo;                            // count of tau < t  (active positives)
        lo = 0; hi = nn;
        while (lo < hi) { int mid = (lo + hi) >> 1; if (sThn[mid] <= tv) lo = mid + 1; else hi = mid; }
        int j = lo;                            // actives negatives = [j, nn)
        #pragma unroll
        for (int l = 0; l < NLAY; l++) {
            float4 A = sPA[i * NLAY + l], A2 = sSA[j * NLAY + l];
            float4 B = sPB[i * NLAY + l], B2 = sSB[j * NLAY + l];
            float4 C = sCB[l];
            float4 r;
            r.x = tv * (A.x + A2.x) + B.x + B2.x + C.x;
            r.y = tv * (A.y + A2.y) + B.y + B2.y + C.y;
            r.z = tv * (A.z + A2.z) + B.z + B2.z + C.z;
            r.w = tv * (A.w + A2.w) + B.w + B2.w + C.w;
            g_aedge_all[l * EE + p] = r;
        }
    }
}

// ---------------- GEMM (64x128 tile, persistent grid) + fused a_src/a_dst ----------------
#define GROWS 64
__global__ __launch_bounds__(256) void k_gemm(const float* __restrict__ W,
                                              const float* __restrict__ atts,
                                              const float* __restrict__ attd) {
    extern __shared__ float smem[];
    float* Ws = smem;              // 128*128
    float* Xs = smem + HCC * HCC;  // 64*128
    int t = threadIdx.x;
    int tx = t & 15, ty = t >> 4;
    // load W once per block
    const float4* W4 = (const float4*)W;
    float4* Ws4 = (float4*)Ws;
    #pragma unroll
    for (int i = 0; i < 16; i++) Ws4[t + 256 * i] = W4[t + 256 * i];
    // att vectors for this thread's 8 columns
    float4 as0 = ((const float4*)atts)[tx * 2], as1 = ((const float4*)atts)[tx * 2 + 1];
    float4 ad0 = ((const float4*)attd)[tx * 2], ad1 = ((const float4*)attd)[tx * 2 + 1];

    for (int tile = blockIdx.x; tile * GROWS < NN; tile += gridDim.x) {
        int base = tile * GROWS;
        __syncthreads();
        float4* Xs4 = (float4*)Xs;
        #pragma unroll
        for (int i = 0; i < 8; i++) {
            int idx = t + 256 * i;
            int r = base + (idx >> 5);
            Xs4[idx] = (r < NN) ? ((const float4*)g_h)[r * 32 + (idx & 31)]
                                : make_float4(0.f, 0.f, 0.f, 0.f);
        }
        __syncthreads();
        float acc[4][8];
        #pragma unroll
        for (int i = 0; i < 4; i++)
            #pragma unroll
            for (int j = 0; j < 8; j++) acc[i][j] = 0.f;
        #pragma unroll 2
        for (int k4 = 0; k4 < 32; k4++) {
            int k = k4 * 4;
            float a[4][4];
            #pragma unroll
            for (int i = 0; i < 4; i++) {
                float4 av = *(const float4*)&Xs[(ty * 4 + i) * HCC + k];
                a[i][0] = av.x; a[i][1] = av.y; a[i][2] = av.z; a[i][3] = av.w;
            }
            #pragma unroll
            for (int j = 0; j < 4; j++) {
                float4 b0 = *(const float4*)&Ws[(k + j) * HCC + tx * 8];
                float4 b1 = *(const float4*)&Ws[(k + j) * HCC + tx * 8 + 4];
                #pragma unroll
                for (int i = 0; i < 4; i++) {
                    float av = a[i][j];
                    acc[i][0] += av * b0.x; acc[i][1] += av * b0.y;
                    acc[i][2] += av * b0.z; acc[i][3] += av * b0.w;
                    acc[i][4] += av * b1.x; acc[i][5] += av * b1.y;
                    acc[i][6] += av * b1.z; acc[i][7] += av * b1.w;
                }
            }
        }
        // store hp + fused attention scalars
        #pragma unroll
        for (int i = 0; i < 4; i++) {
            int r = base + ty * 4 + i;
            float vs = acc[i][0] * as0.x + acc[i][1] * as0.y + acc[i][2] * as0.z + acc[i][3] * as0.w
                     + acc[i][4] * as1.x + acc[i][5] * as1.y + acc[i][6] * as1.z + acc[i][7] * as1.w;
            float vd = acc[i][0] * ad0.x + acc[i][1] * ad0.y + acc[i][2] * ad0.z + acc[i][3] * ad0.w
                     + acc[i][4] * ad1.x + acc[i][5] * ad1.y + acc[i][6] * ad1.z + acc[i][7] * ad1.w;
            vs += __shfl_xor_sync(~0u, vs, 1); vs += __shfl_xor_sync(~0u, vs, 2);
            vd += __shfl_xor_sync(~0u, vd, 1); vd += __shfl_xor_sync(~0u, vd, 2);
            if (r < NN) {
                *(float4*)&g_hp[r * HCC + tx * 8]     = make_float4(acc[i][0], acc[i][1], acc[i][2], acc[i][3]);
                *(float4*)&g_hp[r * HCC + tx * 8 + 4] = make_float4(acc[i][4], acc[i][5], acc[i][6], acc[i][7]);
                if ((tx & 3) == 0) {
                    g_asrc[r * NHH + (tx >> 2)] = vs;
                    g_adst[r * NHH + (tx >> 2)] = vd;
                }
            }
        }
    }
}

// ---------------- softmax-aggregate + bias + LN + relu + residual ----------------
__global__ void k_agg(const float* __restrict__ bias, const float* __restrict__ gam,
                      const float* __restrict__ bet, int layer) {
    int t = threadIdx.x;
    int n = blockIdx.x * 8 + (t >> 5);
    if (n >= NN) return;
    int lane = t & 31;
    int o0 = g_off[n];
    int deg = g_off[n + 1] - o0;
    float4 adn = *(float4*)&g_adst[n * NHH];
    const float4* ae4 = g_aedge_all + (size_t)layer * EE;
    const float* aef = (const float*)ae4;

    const float NEG = -1e30f;
    float m0 = NEG, m1 = NEG, m2 = NEG, m3 = NEG;
    float d0 = 0, d1 = 0, d2 = 0, d3 = 0;
    for (int j = lane; j < deg; j += 32) {
        int s = g_csr_src[o0 + j];
        float4 as = *(float4*)&g_asrc[s * NHH];
        float4 ae = ae4[o0 + j];
        float a0 = as.x + adn.x + ae.x; a0 = a0 >= 0.f ? a0 : 0.2f * a0;
        float a1 = as.y + adn.y + ae.y; a1 = a1 >= 0.f ? a1 : 0.2f * a1;
        float a2 = as.z + adn.z + ae.z; a2 = a2 >= 0.f ? a2 : 0.2f * a2;
        float a3 = as.w + adn.w + ae.w; a3 = a3 >= 0.f ? a3 : 0.2f * a3;
        softmax_upd(m0, d0, a0); softmax_upd(m1, d1, a1);
        softmax_upd(m2, d2, a2); softmax_upd(m3, d3, a3);
    }
    #pragma unroll
    for (int o = 16; o; o >>= 1) {
        float om, od;
        om = __shfl_xor_sync(~0u, m0, o); od = __shfl_xor_sync(~0u, d0, o); softmax_comb(m0, d0, om, od);
        om = __shfl_xor_sync(~0u, m1, o); od = __shfl_xor_sync(~0u, d1, o); softmax_comb(m1, d1, om, od);
        om = __shfl_xor_sync(~0u, m2, o); od = __shfl_xor_sync(~0u, d2, o); softmax_comb(m2, d2, om, od);
        om = __shfl_xor_sync(~0u, m3, o); od = __shfl_xor_sync(~0u, d3, o); softmax_comb(m3, d3, om, od);
    }
    float rd0 = d0 > 0.f ? 1.f / d0 : 0.f;
    float rd1 = d1 > 0.f ? 1.f / d1 : 0.f;
    float rd2 = d2 > 0.f ? 1.f / d2 : 0.f;
    float rd3 = d3 > 0.f ? 1.f / d3 : 0.f;

    int hh = lane >> 3;
    float mh  = (hh & 2) ? ((hh & 1) ? m3 : m2) : ((hh & 1) ? m1 : m0);
    float rdh = (hh & 2) ? ((hh & 1) ? rd3 : rd2) : ((hh & 1) ? rd1 : rd0);
    float adh = (hh & 2) ? ((hh & 1) ? adn.w : adn.z) : ((hh & 1) ? adn.y : adn.x);

    float4 acc = make_float4(0, 0, 0, 0);
    int j = 0;
    for (; j + 1 < deg; j += 2) {
        int p0 = o0 + j, p1 = o0 + j + 1;
        int s0 = g_csr_src[p0], s1 = g_csr_src[p1];
        float as0 = g_asrc[s0 * NHH + hh], as1 = g_asrc[s1 * NHH + hh];
        float ae0 = aef[p0 * 4 + hh], ae1 = aef[p1 * 4 + hh];
        float4 hp0 = ((const float4*)g_hp)[s0 * 32 + lane];
        float4 hp1 = ((const float4*)g_hp)[s1 * 32 + lane];
        float a0 = as0 + adh + ae0; a0 = a0 >= 0.f ? a0 : 0.2f * a0;
        float a1 = as1 + adh + ae1; a1 = a1 >= 0.f ? a1 : 0.2f * a1;
        float w0 = __expf(a0 - mh) * rdh;
        float w1 = __expf(a1 - mh) * rdh;
        acc.x += w0 * hp0.x + w1 * hp1.x;
        acc.y += w0 * hp0.y + w1 * hp1.y;
        acc.z += w0 * hp0.z + w1 * hp1.z;
        acc.w += w0 * hp0.w + w1 * hp1.w;
    }
    if (j < deg) {
        int p = o0 + j;
        int s = g_csr_src[p];
        float a = g_asrc[s * NHH + hh] + adh + aef[p * 4 + hh];
        a = a >= 0.f ? a : 0.2f * a;
        float w = __expf(a - mh) * rdh;
        float4 hp = ((const float4*)g_hp)[s * 32 + lane];
        acc.x += w * hp.x; acc.y += w * hp.y; acc.z += w * hp.z; acc.w += w * hp.w;
    }

    float4 bv = ((const float4*)bias)[lane];
    float4 v = make_float4(acc.x + bv.x, acc.y + bv.y, acc.z + bv.z, acc.w + bv.w);
    float s1 = v.x + v.y + v.z + v.w;
    float s2 = v.x * v.x + v.y * v.y + v.z * v.z + v.w * v.w;
    #pragma unroll
    for (int o = 16; o; o >>= 1) {
        s1 += __shfl_xor_sync(~0u, s1, o);
        s2 += __shfl_xor_sync(~0u, s2, o);
    }
    float mean = s1 * (1.f / HCC);
    float var = s2 * (1.f / HCC) - mean * mean;
    float rstd = rsqrtf(var + 1e-5f);
    float4 gv = ((const float4*)gam)[lane];
    float4 bev = ((const float4*)bet)[lane];
    float4 hold = ((const float4*)g_h)[n * 32 + lane];
    float4 r;
    r.x = hold.x + fmaxf((v.x - mean) * rstd * gv.x + bev.x, 0.f);
    r.y = hold.y + fmaxf((v.y - mean) * rstd * gv.y + bev.y, 0.f);
    r.z = hold.z + fmaxf((v.z - mean) * rstd * gv.z + bev.z, 0.f);
    r.w = hold.w + fmaxf((v.w - mean) * rstd * gv.w + bev.w, 0.f);
    ((float4*)g_h)[n * 32 + lane] = r;
}

// ---------------- pooling + classifier ----------------
__global__ void k_count(const int* __restrict__ batch) {
    int i = blockIdx.x * blockDim.x + threadIdx.x;
    if (i < NN) atomicAdd(&g_cnt[batch[i]], 1.f);
}
__global__ void k_pool(const int* __restrict__ batch) {
    int n0 = blockIdx.x * 256;
    int n1 = n0 + 256; if (n1 > NN) n1 = NN;
    int c = threadIdx.x;
    float run = 0.f;
    int curb = batch[n0];
    for (int n = n0; n < n1; n++) {
        int b = batch[n];
        if (b != curb) {
            atomicAdd(&g_sums[curb * HCC + c], run);
            run = 0.f; curb = b;
        }
        run += g_h[n * HCC + c];
    }
    atomicAdd(&g_sums[curb * HCC + c], run);
}
__global__ void k_cls(const float* __restrict__ W1, const float* __restrict__ b1,
                      const float* __restrict__ W2, const float* __restrict__ b2,
                      float* __restrict__ out) {
    __shared__ float sp[HCC];
    __shared__ float sz[64];
    int b = blockIdx.x;
    int c = threadIdx.x;
    float cnt = fmaxf(g_cnt[b], 1.f);
    sp[c] = g_sums[b * HCC + c] / cnt;
    __syncthreads();
    if (c < 64) {
        float a = b1[c];
        #pragma unroll 4
        for (int k = 0; k < HCC; k++) a += sp[k] * W1[k * 64 + c];
        sz[c] = fmaxf(a, 0.f);
    }
    __syncthreads();
    if (c < NCLS) {
        float a = b2[c];
        #pragma unroll 4
        for (int k = 0; k < 64; k++) a += sz[k] * W2[k * NCLS + c];
        out[b * NCLS + c] = a;
    }
}

// ---------------- launch ----------------
extern "C" void kernel_launch(void* const* d_in, const int* in_sizes, int n_in,
                              void* d_out, int out_size) {
    (void)in_sizes; (void)n_in; (void)out_size;
    const float* x     = (const float*)d_in[0];
    const float* eattr = (const float*)d_in[1];
    const int*   eidx  = (const int*)d_in[2];
    const int*   batch = (const int*)d_in[3];
    const float* W_ne  = (const float*)d_in[4];
    const float* b_ne  = (const float*)d_in[5];
    const float* g_ne  = (const float*)d_in[6];
    const float* be_ne = (const float*)d_in[7];
    const float* W_ee  = (const float*)d_in[8];
    const float* b_ee  = (const float*)d_in[9];
    const float* Wl    = (const float*)d_in[10];
    const float* att_s = (const float*)d_in[11];
    const float* att_d = (const float*)d_in[12];
    const float* We    = (const float*)d_in[13];
    const float* att_e = (const float*)d_in[14];
    const float* b_l   = (const float*)d_in[15];
    const float* g_l   = (const float*)d_in[16];
    const float* be_l  = (const float*)d_in[17];
    const float* W1    = (const float*)d_in[18];
    const float* b1    = (const float*)d_in[19];
    const float* W2    = (const float*)d_in[20];
    const float* b2    = (const float*)d_in[21];
    float* out = (float*)d_out;

    const int* src = eidx;
    const int* dst = eidx + EE;

    const int SMEM_GEMM = (HCC * HCC + GROWS * HCC) * 4;   // 96 KB
    cudaFuncSetAttribute(k_gemm, cudaFuncAttributeMaxDynamicSharedMemorySize, SMEM_GEMM);

    // CSR build + zero
    k_zero<<<(NN + 255) / 256, 256>>>();
    k_hist<<<(EE + 255) / 256, 256>>>(dst);
    k_scan1<<<49, 1024>>>();
    k_scan2<<<1, 64>>>();
    k_scan3<<<(NN + 255) / 256, 256>>>();
    k_scatter<<<(EE + 255) / 256, 256>>>(src, dst, eattr);

    // piecewise a_edge tables + all-layer edge attention logits
    k_prep<<<1, HCC>>>(We, att_e, W_ee, b_ee);
    k_aedge_all<<<592, 256>>>();

    // node encoder
    k_node_enc<<<(NN + 7) / 8, 256>>>(x, W_ne, b_ne, g_ne, be_ne);

    for (int l = 0; l < NLAY; l++) {
        k_gemm<<<296, 256, SMEM_GEMM>>>(Wl + l * HCC * HCC, att_s + l * HCC, att_d + l * HCC);
        k_agg<<<(NN + 7) / 8, 256>>>(b_l + l * HCC, g_l + l * HCC, be_l + l * HCC, l);
    }

    // pooling + classifier
    k_count<<<(NN + 255) / 256, 256>>>(batch);
    k_pool<<<(NN + 255) / 256, HCC>>>(batch);
    k_cls<<<NBATCH, HCC>>>(W1, b1, W2, b2, out);
}

// round 6
// speedup vs baseline: 1.6834x; 1.2560x over previous
#include <cuda_runtime.h>

#define NN 50000
#define EE 640000
#define HCC 128
#define NHH 4
#define NLAY 4
#define NBATCH 64
#define NCLS 88

// ---------------- scratch (static device globals; no allocation) ----------------
__device__ float g_h[NN * HCC];
__device__ float g_hp[NN * HCC];
__device__ float g_asrc[NN * NHH];
__device__ float g_adst[NN * NHH];
__device__ int   g_deg[NN];
__device__ int   g_off[NN + 1];
__device__ int   g_cur[NN];
__device__ int   g_bsum[64];
__device__ int   g_csr_src[EE];
__device__ float g_tcsr[EE];
__device__ uchar2 g_ij[EE];                 // breakpoint interval indices per edge
__device__ float g_sums[NBATCH * HCC];
__device__ float g_cnt[NBATCH];

// piecewise-linear a_edge tables
__device__ int   d_np, d_nn2;
__device__ float d_thrp[HCC], d_thrn[HCC];
__device__ float4 d_PA[(HCC + 1) * NLAY];
__device__ float4 d_PB[(HCC + 1) * NLAY];
__device__ float4 d_SA[(HCC + 1) * NLAY];
__device__ float4 d_SB[(HCC + 1) * NLAY];
__device__ float4 d_CB[NLAY];

// ---------------- zero ----------------
__global__ void k_zero() {
    int i = blockIdx.x * blockDim.x + threadIdx.x;
    if (i < NN) g_deg[i] = 0;
    if (i < NBATCH * HCC) g_sums[i] = 0.f;
    if (i < NBATCH) g_cnt[i] = 0.f;
}

// ---------------- CSR build ----------------
__global__ void k_hist(const int* __restrict__ dst) {
    int i = blockIdx.x * blockDim.x + threadIdx.x;
    if (i < EE) atomicAdd(&g_deg[dst[i]], 1);
}
__global__ void k_scan1() {
    __shared__ int ws[32];
    int t = threadIdx.x;
    int gi = blockIdx.x * 1024 + t;
    int v = (gi < NN) ? g_deg[gi] : 0;
    int lane = t & 31, wid = t >> 5;
    int x = v;
    #pragma unroll
    for (int o = 1; o < 32; o <<= 1) {
        int y = __shfl_up_sync(~0u, x, o);
        if (lane >= o) x += y;
    }
    if (lane == 31) ws[wid] = x;
    __syncthreads();
    if (wid == 0) {
        int y = ws[lane];
        #pragma unroll
        for (int o = 1; o < 32; o <<= 1) {
            int z = __shfl_up_sync(~0u, y, o);
            if (lane >= o) y += z;
        }
        ws[lane] = y;
    }
    __syncthreads();
    int excl = x - v + (wid ? ws[wid - 1] : 0);
    if (gi < NN) g_off[gi] = excl;
    if (t == 1023) g_bsum[blockIdx.x] = excl + v;
}
__global__ void k_scan2() {
    __shared__ int sm2[64];
    int t = threadIdx.x;
    int v = (t < 49) ? g_bsum[t] : 0;
    sm2[t] = v;
    __syncthreads();
    #pragma unroll
    for (int o = 1; o < 64; o <<= 1) {
        int x = (t >= o) ? sm2[t - o] : 0;
        __syncthreads();
        sm2[t] += x;
        __syncthreads();
    }
    if (t < 49) g_bsum[t] = sm2[t] - v;
}
__global__ void k_scan3() {
    int i = blockIdx.x * blockDim.x + threadIdx.x;
    if (i < NN) {
        int o = g_off[i] + g_bsum[i >> 10];
        g_off[i] = o;
        g_cur[i] = o;
    }
    if (i == 0) g_off[NN] = EE;
}
// scatter + per-edge breakpoint interval indices (needs k_prep tables first)
__global__ void k_scatter(const int* __restrict__ src, const int* __restrict__ dst,
                          const float* __restrict__ eattr) {
    int i = blockIdx.x * blockDim.x + threadIdx.x;
    if (i >= EE) return;
    int p = atomicAdd(&g_cur[dst[i]], 1);
    float tv = eattr[i];
    g_csr_src[p] = src[i];
    g_tcsr[p] = tv;
    int np = d_np, nn = d_nn2;
    int lo = 0, hi = np;
    while (lo < hi) { int m = (lo + hi) >> 1; if (d_thrp[m] < tv) lo = m + 1; else hi = m; }
    int ii = lo;
    lo = 0; hi = nn;
    while (lo < hi) { int m = (lo + hi) >> 1; if (d_thrn[m] <= tv) lo = m + 1; else hi = m; }
    g_ij[p] = make_uchar2((unsigned char)ii, (unsigned char)lo);
}

// ---------------- node encoder ----------------
__global__ void k_node_enc(const float* __restrict__ x, const float* __restrict__ W,
                           const float* __restrict__ b, const float* __restrict__ g,
                           const float* __restrict__ be) {
    int t = threadIdx.x;
    int n = blockIdx.x * 8 + (t >> 5);
    if (n >= NN) return;
    int lane = t & 31;
    float4 xv = ((const float4*)x)[n];
    const float4* Wr = (const float4*)W;
    float4 w0 = Wr[lane], w1 = Wr[32 + lane], w2 = Wr[64 + lane], w3 = Wr[96 + lane];
    float4 bv = ((const float4*)b)[lane];
    float4 y;
    y.x = bv.x + xv.x * w0.x + xv.y * w1.x + xv.z * w2.x + xv.w * w3.x;
    y.y = bv.y + xv.x * w0.y + xv.y * w1.y + xv.z * w2.y + xv.w * w3.y;
    y.z = bv.z + xv.x * w0.z + xv.y * w1.z + xv.z * w2.z + xv.w * w3.z;
    y.w = bv.w + xv.x * w0.w + xv.y * w1.w + xv.z * w2.w + xv.w * w3.w;
    float s1 = y.x + y.y + y.z + y.w;
    float s2 = y.x * y.x + y.y * y.y + y.z * y.z + y.w * y.w;
    #pragma unroll
    for (int o = 16; o; o >>= 1) {
        s1 += __shfl_xor_sync(~0u, s1, o);
        s2 += __shfl_xor_sync(~0u, s2, o);
    }
    float mean = s1 * (1.f / HCC);
    float var = s2 * (1.f / HCC) - mean * mean;
    float rstd = rsqrtf(var + 1e-5f);
    float4 gv = ((const float4*)g)[lane];
    float4 bev = ((const float4*)be)[lane];
    float4 r;
    r.x = fmaxf((y.x - mean) * rstd * gv.x + bev.x, 0.f);
    r.y = fmaxf((y.y - mean) * rstd * gv.y + bev.y, 0.f);
    r.z = fmaxf((y.z - mean) * rstd * gv.z + bev.z, 0.f);
    r.w = fmaxf((y.w - mean) * rstd * gv.w + bev.w, 0.f);
    ((float4*)g_h)[n * 32 + lane] = r;
}

// ---------------- piecewise a_edge tables (1 block, 128 threads) ----------------
__global__ void k_prep(const float* __restrict__ We, const float* __restrict__ atte,
                       const float* __restrict__ Wee, const float* __restrict__ bee) {
    __shared__ float stau[HCC], sw_[HCC], sb_[HCC];
    __shared__ int sflag[HCC];
    __shared__ float swm[NLAY * NHH][HCC];
    __shared__ float sbm[NLAY * NHH][HCC];
    __shared__ int srtp[HCC], srtn[HCC];
    __shared__ int s_np, s_nn;
    int k = threadIdx.x;
    if (k == 0) { s_np = 0; s_nn = 0; }
    float w = Wee[k], b = bee[k];
    #pragma unroll
    for (int l = 0; l < NLAY; l++) {
        #pragma unroll
        for (int h = 0; h < NHH; h++) {
            float m = 0.f;
            #pragma unroll 8
            for (int c = 0; c < 32; c++)
                m += We[l * HCC * HCC + k * HCC + h * 32 + c] * atte[l * HCC + h * 32 + c];
            swm[l * NHH + h][k] = w * m;
            sbm[l * NHH + h][k] = b * m;
        }
    }
    sw_[k] = w; sb_[k] = b;
    int flag = (w > 0.f) ? 0 : ((w < 0.f) ? 1 : 2);
    sflag[k] = flag;
    stau[k] = (flag < 2) ? (-b / w) : 0.f;
    __syncthreads();
    float tk = stau[k];
    int rank = 0, cnt = 0;
    if (flag < 2) {
        for (int j = 0; j < HCC; j++)
            if (sflag[j] == flag) {
                cnt++;
                if (stau[j] < tk || (stau[j] == tk && j < k)) rank++;
            }
    }
    if (flag == 0 && rank == 0) s_np = cnt;
    if (flag == 1 && rank == 0) s_nn = cnt;
    if (flag == 0) { srtp[rank] = k; d_thrp[rank] = tk; }
    if (flag == 1) { srtn[rank] = k; d_thrn[rank] = tk; }
    __syncthreads();
    int np = s_np, nn = s_nn;
    float* PAf = (float*)d_PA; float* PBf = (float*)d_PB;
    float* SAf = (float*)d_SA; float* SBf = (float*)d_SB;
    float* CBf = (float*)d_CB;
    if (k < 16) {
        int c = k, l = k >> 2, h = k & 3;
        float ra = 0.f, rb = 0.f;
        PAf[(0 * NLAY + l) * 4 + h] = 0.f;
        PBf[(0 * NLAY + l) * 4 + h] = 0.f;
        for (int i = 0; i < np; i++) {
            int kk = srtp[i];
            ra += swm[c][kk]; rb += sbm[c][kk];
            PAf[((i + 1) * NLAY + l) * 4 + h] = ra;
            PBf[((i + 1) * NLAY + l) * 4 + h] = rb;
        }
    } else if (k < 32) {
        int c = k - 16, l = c >> 2, h = c & 3;
        float ra = 0.f, rb = 0.f;
        SAf[(nn * NLAY + l) * 4 + h] = 0.f;
        SBf[(nn * NLAY + l) * 4 + h] = 0.f;
        for (int i = nn - 1; i >= 0; i--) {
            int kk = srtn[i];
            ra += swm[c][kk]; rb += sbm[c][kk];
            SAf[(i * NLAY + l) * 4 + h] = ra;
            SBf[(i * NLAY + l) * 4 + h] = rb;
        }
    } else if (k < 48) {
        int c = k - 32;
        float r = 0.f;
        for (int j = 0; j < HCC; j++)
            if (sflag[j] == 2 && sb_[j] > 0.f) r += sbm[c][j];
        CBf[c] = r;
    }
    if (k == 0) { d_np = np; d_nn2 = nn; }
}

// ---------------- GEMM: 128x128 tile, 8x8 micro-tile, K split 64, persistent ----------------
#define GM 128
__global__ __launch_bounds__(256, 2) void k_gemm(const float* __restrict__ W) {
    extern __shared__ float smem[];
    float* Ws = smem;               // [128][128]  (k-major, same as input)
    float* Xs = smem + HCC * HCC;   // [64][128]   (k-major transposed chunk)
    int t = threadIdx.x;
    int tx = t & 15, ty = t >> 4;
    const float4* W4 = (const float4*)W;
    float4* Ws4 = (float4*)Ws;
    #pragma unroll
    for (int i = 0; i < 16; i++) Ws4[t + 256 * i] = W4[t + 256 * i];

    int nt = (NN + GM - 1) / GM;
    for (int tile = blockIdx.x; tile < nt; tile += gridDim.x) {
        int base = tile * GM;
        float acc[8][8];
        #pragma unroll
        for (int i = 0; i < 8; i++)
            #pragma unroll
            for (int j = 0; j < 8; j++) acc[i][j] = 0.f;
        #pragma unroll
        for (int kc = 0; kc < 2; kc++) {
            __syncthreads();
            // load+transpose X chunk: thread t covers row r = t>>1, 8 float4s
            int r = t >> 1;
            int gr = base + r;
            #pragma unroll
            for (int i = 0; i < 8; i++) {
                int fc = (t & 1) * 8 + i;            // float4 index within 64-float chunk row
                float4 v = (gr < NN) ? ((const float4*)g_h)[gr * 32 + kc * 16 + fc]
                                     : make_float4(0.f, 0.f, 0.f, 0.f);
                int kl = fc * 4;
                Xs[(kl + 0) * GM + r] = v.x;
                Xs[(kl + 1) * GM + r] = v.y;
                Xs[(kl + 2) * GM + r] = v.z;
                Xs[(kl + 3) * GM + r] = v.w;
            }
            __syncthreads();
            #pragma unroll 4
            for (int k = 0; k < 64; k++) {
                float4 a0 = *(const float4*)&Xs[k * GM + ty * 4];
                float4 a1 = *(const float4*)&Xs[k * GM + 64 + ty * 4];
                float4 b0 = *(const float4*)&Ws[(kc * 64 + k) * HCC + tx * 4];
                float4 b1 = *(const float4*)&Ws[(kc * 64 + k) * HCC + 64 + tx * 4];
                float ar[8] = {a0.x, a0.y, a0.z, a0.w, a1.x, a1.y, a1.z, a1.w};
                float bc[8] = {b0.x, b0.y, b0.z, b0.w, b1.x, b1.y, b1.z, b1.w};
                #pragma unroll
                for (int i = 0; i < 8; i++)
                    #pragma unroll
                    for (int j = 0; j < 8; j++)
                        acc[i][j] += ar[i] * bc[j];
            }
        }
        #pragma unroll
        for (int i = 0; i < 8; i++) {
            int r = base + ((i < 4) ? (ty * 4 + i) : (64 + ty * 4 + i - 4));
            if (r < NN) {
                *(float4*)&g_hp[r * HCC + tx * 4]      = make_float4(acc[i][0], acc[i][1], acc[i][2], acc[i][3]);
                *(float4*)&g_hp[r * HCC + 64 + tx * 4] = make_float4(acc[i][4], acc[i][5], acc[i][6], acc[i][7]);
            }
        }
    }
}

// ---------------- a_src / a_dst from g_hp ----------------
__global__ void k_attn(const float* __restrict__ atts, const float* __restrict__ attd) {
    __shared__ float ss[HCC], sd[HCC];
    int t = threadIdx.x;
    if (t < HCC) { ss[t] = atts[t]; sd[t] = attd[t]; }
    __syncthreads();
    int n = blockIdx.x * 8 + (t >> 5);
    if (n >= NN) return;
    int lane = t & 31;
    float4 p = ((const float4*)g_hp)[n * 32 + lane];
    int c = lane * 4;
    float vs = p.x * ss[c] + p.y * ss[c + 1] + p.z * ss[c + 2] + p.w * ss[c + 3];
    float vd = p.x * sd[c] + p.y * sd[c + 1] + p.z * sd[c + 2] + p.w * sd[c + 3];
    #pragma unroll
    for (int o = 4; o; o >>= 1) {
        vs += __shfl_xor_sync(~0u, vs, o);
        vd += __shfl_xor_sync(~0u, vd, o);
    }
    if ((lane & 7) == 0) {
        g_asrc[n * NHH + (lane >> 3)] = vs;
        g_adst[n * NHH + (lane >> 3)] = vd;
    }
}

// ---------------- single-pass softmax-aggregate + bias + LN + relu + residual ----------------
__global__ void k_agg(const float* __restrict__ bias, const float* __restrict__ gam,
                      const float* __restrict__ bet, int layer) {
    int t = threadIdx.x;
    int n = blockIdx.x * 8 + (t >> 5);
    if (n >= NN) return;
    int lane = t & 31;
    int hh = lane >> 3;
    int o0 = g_off[n];
    int deg = g_off[n + 1] - o0;
    float adh = g_adst[n * NHH + hh];
    const float* PAf = (const float*)d_PA + layer * 4 + hh;   // index stride 16 per i
    const float* PBf = (const float*)d_PB + layer * 4 + hh;
    const float* SAf = (const float*)d_SA + layer * 4 + hh;
    const float* SBf = (const float*)d_SB + layer * 4 + hh;
    float cb = ((const float*)d_CB)[layer * 4 + hh];
    const float4* hp4 = (const float4*)g_hp;

    float4 acc = make_float4(0.f, 0.f, 0.f, 0.f);
    float den = 0.f;
    int j = 0;
    for (; j + 1 < deg; j += 2) {
        int p0 = o0 + j, p1 = o0 + j + 1;
        int s0 = g_csr_src[p0], s1 = g_csr_src[p1];
        float tv0 = g_tcsr[p0], tv1 = g_tcsr[p1];
        uchar2 ij0 = g_ij[p0], ij1 = g_ij[p1];
        float as0 = g_asrc[s0 * NHH + hh], as1 = g_asrc[s1 * NHH + hh];
        float4 hp0 = hp4[s0 * 32 + lane];
        float4 hp1 = hp4[s1 * 32 + lane];
        float ae0 = tv0 * (PAf[ij0.x * 16] + SAf[ij0.y * 16]) + PBf[ij0.x * 16] + SBf[ij0.y * 16] + cb;
        float ae1 = tv1 * (PAf[ij1.x * 16] + SAf[ij1.y * 16]) + PBf[ij1.x * 16] + SBf[ij1.y * 16] + cb;
        float a0 = as0 + adh + ae0; a0 = a0 >= 0.f ? a0 : 0.2f * a0;
        float a1 = as1 + adh + ae1; a1 = a1 >= 0.f ? a1 : 0.2f * a1;
        float w0 = __expf(a0);
        float w1 = __expf(a1);
        den += w0 + w1;
        acc.x += w0 * hp0.x + w1 * hp1.x;
        acc.y += w0 * hp0.y + w1 * hp1.y;
        acc.z += w0 * hp0.z + w1 * hp1.z;
        acc.w += w0 * hp0.w + w1 * hp1.w;
    }
    if (j < deg) {
        int p = o0 + j;
        int s = g_csr_src[p];
        float tv = g_tcsr[p];
        uchar2 ij = g_ij[p];
        float ae = tv * (PAf[ij.x * 16] + SAf[ij.y * 16]) + PBf[ij.x * 16] + SBf[ij.y * 16] + cb;
        float a = g_asrc[s * NHH + hh] + adh + ae;
        a = a >= 0.f ? a : 0.2f * a;
        float w = __expf(a);
        float4 hp = hp4[s * 32 + lane];
        den += w;
        acc.x += w * hp.x; acc.y += w * hp.y; acc.z += w * hp.z; acc.w += w * hp.w;
    }
    float rden = den > 0.f ? 1.f / den : 0.f;

    float4 bv = ((const float4*)bias)[lane];
    float4 v = make_float4(acc.x * rden + bv.x, acc.y * rden + bv.y,
                           acc.z * rden + bv.z, acc.w * rden + bv.w);
    float s1 = v.x + v.y + v.z + v.w;
    float s2 = v.x * v.x + v.y * v.y + v.z * v.z + v.w * v.w;
    #pragma unroll
    for (int o = 16; o; o >>= 1) {
        s1 += __shfl_xor_sync(~0u, s1, o);
        s2 += __shfl_xor_sync(~0u, s2, o);
    }
    float mean = s1 * (1.f / HCC);
    float var = s2 * (1.f / HCC) - mean * mean;
    float rstd = rsqrtf(var + 1e-5f);
    float4 gv = ((const float4*)gam)[lane];
    float4 bev = ((const float4*)bet)[lane];
    float4 hold = ((const float4*)g_h)[n * 32 + lane];
    float4 r;
    r.x = hold.x + fmaxf((v.x - mean) * rstd * gv.x + bev.x, 0.f);
    r.y = hold.y + fmaxf((v.y - mean) * rstd * gv.y + bev.y, 0.f);
    r.z = hold.z + fmaxf((v.z - mean) * rstd * gv.z + bev.z, 0.f);
    r.w = hold.w + fmaxf((v.w - mean) * rstd * gv.w + bev.w, 0.f);
    ((float4*)g_h)[n * 32 + lane] = r;
}

// ---------------- pooling + classifier ----------------
__global__ void k_count(const int* __restrict__ batch) {
    int i = blockIdx.x * blockDim.x + threadIdx.x;
    if (i < NN) atomicAdd(&g_cnt[batch[i]], 1.f);
}
__global__ void k_pool(const int* __restrict__ batch) {
    int n0 = blockIdx.x * 256;
    int n1 = n0 + 256; if (n1 > NN) n1 = NN;
    int c = threadIdx.x;
    float run = 0.f;
    int curb = batch[n0];
    for (int n = n0; n < n1; n++) {
        int b = batch[n];
        if (b != curb) {
            atomicAdd(&g_sums[curb * HCC + c], run);
            run = 0.f; curb = b;
        }
        run += g_h[n * HCC + c];
    }
    atomicAdd(&g_sums[curb * HCC + c], run);
}
__global__ void k_cls(const float* __restrict__ W1, const float* __restrict__ b1,
                      const float* __restrict__ W2, const float* __restrict__ b2,
                      float* __restrict__ out) {
    __shared__ float sp[HCC];
    __shared__ float sz[64];
    int b = blockIdx.x;
    int c = threadIdx.x;
    float cnt = fmaxf(g_cnt[b], 1.f);
    sp[c] = g_sums[b * HCC + c] / cnt;
    __syncthreads();
    if (c < 64) {
        float a = b1[c];
        #pragma unroll 4
        for (int k = 0; k < HCC; k++) a += sp[k] * W1[k * 64 + c];
        sz[c] = fmaxf(a, 0.f);
    }
    __syncthreads();
    if (c < NCLS) {
        float a = b2[c];
        #pragma unroll 4
        for (int k = 0; k < 64; k++) a += sz[k] * W2[k * NCLS + c];
        out[b * NCLS + c] = a;
    }
}

// ---------------- launch ----------------
extern "C" void kernel_launch(void* const* d_in, const int* in_sizes, int n_in,
                              void* d_out, int out_size) {
    (void)in_sizes; (void)n_in; (void)out_size;
    const float* x     = (const float*)d_in[0];
    const float* eattr = (const float*)d_in[1];
    const int*   eidx  = (const int*)d_in[2];
    const int*   batch = (const int*)d_in[3];
    const float* W_ne  = (const float*)d_in[4];
    const float* b_ne  = (const float*)d_in[5];
    const float* g_ne  = (const float*)d_in[6];
    const float* be_ne = (const float*)d_in[7];
    const float* W_ee  = (const float*)d_in[8];
    const float* b_ee  = (const float*)d_in[9];
    const float* Wl    = (const float*)d_in[10];
    const float* att_s = (const float*)d_in[11];
    const float* att_d = (const float*)d_in[12];
    const float* We    = (const float*)d_in[13];
    const float* att_e = (const float*)d_in[14];
    const float* b_l   = (const float*)d_in[15];
    const float* g_l   = (const float*)d_in[16];
    const float* be_l  = (const float*)d_in[17];
    const float* W1    = (const float*)d_in[18];
    const float* b1    = (const float*)d_in[19];
    const float* W2    = (const float*)d_in[20];
    const float* b2    = (const float*)d_in[21];
    float* out = (float*)d_out;

    const int* src = eidx;
    const int* dst = eidx + EE;

    const int SMEM_GEMM = (HCC * HCC + 64 * GM) * 4;   // 96 KB
    cudaFuncSetAttribute(k_gemm, cudaFuncAttributeMaxDynamicSharedMemorySize, SMEM_GEMM);

    // tables first (k_scatter needs thresholds)
    k_prep<<<1, HCC>>>(We, att_e, W_ee, b_ee);

    // CSR build + zero
    k_zero<<<(NN + 255) / 256, 256>>>();
    k_hist<<<(EE + 255) / 256, 256>>>(dst);
    k_scan1<<<49, 1024>>>();
    k_scan2<<<1, 64>>>();
    k_scan3<<<(NN + 255) / 256, 256>>>();
    k_scatter<<<(EE + 255) / 256, 256>>>(src, dst, eattr);

    // node encoder
    k_node_enc<<<(NN + 7) / 8, 256>>>(x, W_ne, b_ne, g_ne, be_ne);

    for (int l = 0; l < NLAY; l++) {
        k_gemm<<<296, 256, SMEM_GEMM>>>(Wl + l * HCC * HCC);
        k_attn<<<(NN + 7) / 8, 256>>>(att_s + l * HCC, att_d + l * HCC);
        k_agg<<<(NN + 7) / 8, 256>>>(b_l + l * HCC, g_l + l * HCC, be_l + l * HCC, l);
    }

    // pooling + classifier
    k_count<<<(NN + 255) / 256, 256>>>(batch);
    k_pool<<<(NN + 255) / 256, HCC>>>(batch);
    k_cls<<<NBATCH, HCC>>>(W1, b1, W2, b2, out);
}